// round 1
// baseline (speedup 1.0000x reference)
#include <cuda_runtime.h>
#include <math.h>

// Problem constants (fixed by dataset)
#define NMAX   25000
#define EMAX   400000
#define GMAX   1000
#define HID    185
#define INCH   9
#define JKDIM  (4*HID)   // 740

// ---------------- scratch (device globals, no allocation) ----------------
__device__ float    g_dis[NMAX];            // deg -> rsqrt(deg)
__device__ int      g_cnt[NMAX];
__device__ int      g_offs[NMAX + 1];
__device__ int      g_cursor[NMAX];
__device__ int      g_csr_src[EMAX];
__device__ float    g_csr_w[EMAX];
__device__ float    g_ax[NMAX * INCH];
__device__ float    g_xs[NMAX * JKDIM];     // concat buffer [N,740]
__device__ float    g_tmp[NMAX * HID];
__device__ float    g_hjk[NMAX * HID];
__device__ unsigned g_pool[GMAX * HID];
__device__ float    g_bnscale[4 * HID];
__device__ float    g_bnshift[4 * HID];

// ---------------- helpers ----------------
__device__ __forceinline__ unsigned enc_f(float f) {
    unsigned u = __float_as_uint(f);
    return (u & 0x80000000u) ? ~u : (u | 0x80000000u);
}
__device__ __forceinline__ float dec_f(unsigned e) {
    return (e & 0x80000000u) ? __uint_as_float(e & 0x7FFFFFFFu)
                             : __uint_as_float(~e);
}

// ---------------- kernels ----------------
__global__ void k_init(int N, int G) {
    int i = blockIdx.x * blockDim.x + threadIdx.x;
    if (i < N) { g_dis[i] = 1.0f; g_cnt[i] = 0; }
    if (i < G * HID) g_pool[i] = 0x007FFFFFu;   // enc(-inf)
}

__global__ void k_count(const int* __restrict__ ei, int E) {
    int e = blockIdx.x * blockDim.x + threadIdx.x;
    if (e >= E) return;
    int d = ei[E + e];
    atomicAdd(&g_dis[d], 1.0f);
    atomicAdd(&g_cnt[d], 1);
}

__global__ void k_rsqrt_deg(int N) {
    int i = blockIdx.x * blockDim.x + threadIdx.x;
    if (i < N) g_dis[i] = rsqrtf(g_dis[i]);
}

// single-block scan of g_cnt -> g_offs (exclusive), offs[N] = total
__global__ void k_scan(int N) {
    __shared__ int sums[1024];
    int t = threadIdx.x;
    int chunk = (N + 1023) / 1024;
    int s = t * chunk;
    int e = min(s + chunk, N);
    int acc = 0;
    for (int i = s; i < e; i++) acc += g_cnt[i];
    sums[t] = acc;
    __syncthreads();
    for (int off = 1; off < 1024; off <<= 1) {
        int add = (t >= off) ? sums[t - off] : 0;
        __syncthreads();
        sums[t] += add;
        __syncthreads();
    }
    int run = (t == 0) ? 0 : sums[t - 1];
    for (int i = s; i < e; i++) { g_offs[i] = run; run += g_cnt[i]; }
    if (s < N && e == N) g_offs[N] = run;
}

__global__ void k_cursor(int N) {
    int i = blockIdx.x * blockDim.x + threadIdx.x;
    if (i < N) g_cursor[i] = g_offs[i];
}

__global__ void k_fill(const int* __restrict__ ei, int E) {
    int e = blockIdx.x * blockDim.x + threadIdx.x;
    if (e >= E) return;
    int s = ei[e];
    int d = ei[E + e];
    int p = atomicAdd(&g_cursor[d], 1);
    g_csr_src[p] = s;
    g_csr_w[p]   = g_dis[s];
}

// aggregate raw x (9 channels): warp per node
__global__ void k_aggregate_x(const float* __restrict__ x, int N) {
    int warp = (blockIdx.x * blockDim.x + threadIdx.x) >> 5;
    int lane = threadIdx.x & 31;
    if (warp >= N) return;
    int n = warp;
    int s0 = g_offs[n], s1 = g_offs[n + 1];
    float acc[INCH];
#pragma unroll
    for (int c = 0; c < INCH; c++) acc[c] = 0.f;
    for (int e = s0 + lane; e < s1; e += 32) {
        int s = g_csr_src[e];
        float w = g_csr_w[e];
#pragma unroll
        for (int c = 0; c < INCH; c++) acc[c] += w * x[s * INCH + c];
    }
#pragma unroll
    for (int c = 0; c < INCH; c++)
#pragma unroll
        for (int o = 16; o; o >>= 1)
            acc[c] += __shfl_xor_sync(0xffffffffu, acc[c], o);
    if (lane == 0) {
        float dn = g_dis[n];
#pragma unroll
        for (int c = 0; c < INCH; c++)
            g_ax[n * INCH + c] = dn * acc[c] + dn * dn * x[n * INCH + c];
    }
}

__global__ void k_bn_pre(const float* __restrict__ gamma, const float* __restrict__ beta,
                         const float* __restrict__ mean, const float* __restrict__ var) {
    int i = blockIdx.x * blockDim.x + threadIdx.x;
    if (i < 4 * HID) {
        float sc = gamma[i] * rsqrtf(var[i] + 1e-5f);
        g_bnscale[i] = sc;
        g_bnshift[i] = beta[i] - mean[i] * sc;
    }
}

// ---------------- SGEMM: C[N,M] = A[N,K] @ B[K,M] (+epilogue) ----------------
// mode 0: plain store, mode 1: +bias, mode 2: +bias then bn scale/shift + relu
#define BM 64
#define BN 64
#define BK 16
__global__ void __launch_bounds__(256)
k_sgemm(const float* __restrict__ A, int lda,
        const float* __restrict__ B, int ldb,
        float* __restrict__ C, int ldc,
        int N, int K, int M,
        const float* __restrict__ bias,
        const float* __restrict__ scale,
        const float* __restrict__ shift,
        int mode) {
    __shared__ float As[BK][BM];
    __shared__ float Bs[BK][BN];
    int tid = threadIdx.x;
    int tx = tid & 15;          // col group (0..15) -> 4 cols each
    int ty = tid >> 4;          // row group (0..15) -> 4 rows each
    int rowBase = blockIdx.y * BM;
    int colBase = blockIdx.x * BN;

    float acc[4][4];
#pragma unroll
    for (int i = 0; i < 4; i++)
#pragma unroll
        for (int j = 0; j < 4; j++) acc[i][j] = 0.f;

    for (int kk = 0; kk < K; kk += BK) {
        // load A tile: 64x16, 4 elems/thread, k = tid&15 contiguous -> coalesced
#pragma unroll
        for (int i = 0; i < 4; i++) {
            int r = (tid >> 4) + i * 16;
            int k = tid & 15;
            int gr = rowBase + r, gk = kk + k;
            As[k][r] = (gr < N && gk < K) ? A[gr * lda + gk] : 0.f;
        }
        // load B tile: 16x64, col = tid&63 contiguous -> coalesced
#pragma unroll
        for (int i = 0; i < 4; i++) {
            int k = (tid >> 6) + i * 4;
            int cc = tid & 63;
            int gk = kk + k, gc = colBase + cc;
            Bs[k][cc] = (gk < K && gc < M) ? B[gk * ldb + gc] : 0.f;
        }
        __syncthreads();
#pragma unroll
        for (int k = 0; k < BK; k++) {
            float4 a4 = *(const float4*)&As[k][ty * 4];
            float4 b4 = *(const float4*)&Bs[k][tx * 4];
            float av[4] = {a4.x, a4.y, a4.z, a4.w};
            float bv[4] = {b4.x, b4.y, b4.z, b4.w};
#pragma unroll
            for (int i = 0; i < 4; i++)
#pragma unroll
                for (int j = 0; j < 4; j++)
                    acc[i][j] = fmaf(av[i], bv[j], acc[i][j]);
        }
        __syncthreads();
    }

#pragma unroll
    for (int i = 0; i < 4; i++) {
        int r = rowBase + ty * 4 + i;
        if (r >= N) continue;
#pragma unroll
        for (int j = 0; j < 4; j++) {
            int c = colBase + tx * 4 + j;
            if (c >= M) continue;
            float v = acc[i][j];
            if (mode >= 1) v += bias[c];
            if (mode == 2) v = fmaxf(fmaf(v, scale[c], shift[c]), 0.f);
            C[r * ldc + c] = v;
        }
    }
}

// aggregation for 185-channel hidden layers + bias + bn + relu, writes into XS
__global__ void k_aggregate_h(const float* __restrict__ tmp,
                              const float* __restrict__ bias,
                              const float* __restrict__ scale,
                              const float* __restrict__ shift,
                              int colofs, int N) {
    int n = blockIdx.x;
    int c = threadIdx.x;
    if (n >= N || c >= HID) return;
    int s0 = g_offs[n], s1 = g_offs[n + 1];
    float acc = 0.f;
    int e = s0;
    for (; e + 4 <= s1; e += 4) {
        int i0 = g_csr_src[e],   i1 = g_csr_src[e+1];
        int i2 = g_csr_src[e+2], i3 = g_csr_src[e+3];
        float w0 = g_csr_w[e],   w1 = g_csr_w[e+1];
        float w2 = g_csr_w[e+2], w3 = g_csr_w[e+3];
        acc += w0 * tmp[i0 * HID + c];
        acc += w1 * tmp[i1 * HID + c];
        acc += w2 * tmp[i2 * HID + c];
        acc += w3 * tmp[i3 * HID + c];
    }
    for (; e < s1; ++e) acc += g_csr_w[e] * tmp[g_csr_src[e] * HID + c];
    float dn = g_dis[n];
    float v = dn * acc + dn * dn * tmp[n * HID + c] + bias[c];
    v = fmaxf(fmaf(v, scale[c], shift[c]), 0.f);
    g_xs[n * JKDIM + colofs + c] = v;
}

__global__ void k_pool(const int* __restrict__ batch, int N) {
    int idx = blockIdx.x * blockDim.x + threadIdx.x;
    if (idx >= N * HID) return;
    int n = idx / HID, c = idx - n * HID;
    unsigned u = enc_f(g_hjk[idx]);
    atomicMax(&g_pool[batch[n] * HID + c], u);
}

__global__ void k_finalize(const float* __restrict__ Wout,
                           const float* __restrict__ bout,
                           float* __restrict__ out, int G) {
    int g = blockIdx.x;
    int t = threadIdx.x;
    __shared__ float red[256];
    float p = 0.f;
    for (int c = t; c < HID; c += 256)
        p += dec_f(g_pool[g * HID + c]) * Wout[c];
    red[t] = p;
    __syncthreads();
    for (int o = 128; o; o >>= 1) {
        if (t < o) red[t] += red[t + o];
        __syncthreads();
    }
    if (t == 0) out[g] = red[0] + bout[0];
}

// ---------------- host launcher ----------------
extern "C" void kernel_launch(void* const* d_in, const int* in_sizes, int n_in,
                              void* d_out, int out_size) {
    const float* x       = (const float*)d_in[0];
    const int*   ei      = (const int*)  d_in[1];
    const int*   batch   = (const int*)  d_in[2];
    const float* W0      = (const float*)d_in[3];
    const float* b0      = (const float*)d_in[4];
    const float* W_h     = (const float*)d_in[5];
    const float* b_h     = (const float*)d_in[6];
    const float* bn_g    = (const float*)d_in[7];
    const float* bn_b    = (const float*)d_in[8];
    const float* bn_m    = (const float*)d_in[9];
    const float* bn_v    = (const float*)d_in[10];
    const float* W_jk    = (const float*)d_in[11];
    const float* b_jk    = (const float*)d_in[12];
    const float* W_out   = (const float*)d_in[13];
    const float* b_out   = (const float*)d_in[14];
    float* out = (float*)d_out;

    int N = in_sizes[0] / INCH;
    int E = in_sizes[1] / 2;
    int G = out_size;

    // access device symbol pointers implicitly (kernels use globals directly)
    float* xs0; cudaGetSymbolAddress((void**)&xs0, g_xs);
    float* tmp; cudaGetSymbolAddress((void**)&tmp, g_tmp);
    float* ax;  cudaGetSymbolAddress((void**)&ax,  g_ax);
    float* hjk; cudaGetSymbolAddress((void**)&hjk, g_hjk);
    float* bns; cudaGetSymbolAddress((void**)&bns, g_bnscale);
    float* bnh; cudaGetSymbolAddress((void**)&bnh, g_bnshift);

    int initN = (N > G * HID) ? N : G * HID;
    k_init<<<(initN + 255) / 256, 256>>>(N, G);
    k_count<<<(E + 255) / 256, 256>>>(ei, E);
    k_rsqrt_deg<<<(N + 255) / 256, 256>>>(N);
    k_scan<<<1, 1024>>>(N);
    k_cursor<<<(N + 255) / 256, 256>>>(N);
    k_fill<<<(E + 255) / 256, 256>>>(ei, E);
    k_aggregate_x<<<(N * 32 + 255) / 256, 256>>>(x, N);
    k_bn_pre<<<(4 * HID + 255) / 256, 256>>>(bn_g, bn_b, bn_m, bn_v);

    dim3 grid_g((HID + BN - 1) / BN, (N + BM - 1) / BM);

    // layer 0: (A^ x) @ W0 + b0, bn0, relu -> XS[:,0:185]
    k_sgemm<<<grid_g, 256>>>(ax, INCH, W0, HID, xs0, JKDIM,
                             N, INCH, HID, b0, bns, bnh, 2);

    // layers 1..3
    for (int i = 1; i <= 3; i++) {
        k_sgemm<<<grid_g, 256>>>(xs0 + (i - 1) * HID, JKDIM,
                                 W_h + (i - 1) * HID * HID, HID,
                                 tmp, HID, N, HID, HID,
                                 (const float*)0, (const float*)0, (const float*)0, 0);
        k_aggregate_h<<<N, 192>>>(tmp, b_h + (i - 1) * HID,
                                  bns + i * HID, bnh + i * HID, i * HID, N);
    }

    // JK: XS[N,740] @ W_jk + b_jk -> hjk[N,185]
    k_sgemm<<<grid_g, 256>>>(xs0, JKDIM, W_jk, HID, hjk, HID,
                             N, JKDIM, HID, b_jk, (const float*)0, (const float*)0, 1);

    k_pool<<<(N * HID + 255) / 256, 256>>>(batch, N);
    k_finalize<<<G, 256>>>(W_out, b_out, out, G);
}